// round 5
// baseline (speedup 1.0000x reference)
#include <cuda_runtime.h>

// EdgeModel: out = L2( silu( L1( silu( L0( cat[edge,src,dest] ) ) ) ) )
// Fused 3-layer MLP, fp32 exact math via packed fma.rn.f32x2 (2x fp32 pipe).
//
// Tile: 64 rows/block, 256 threads, thread = 4 rows x 4 col-pairs (8 cols).
// Activations live in SMEM across all 3 layers; weights streamed in 32-row
// chunks through a 16KB SMEM buffer. Total static SMEM = 48KB exactly.

#define TM 64
#define KC 32
#define DH 128

typedef unsigned long long u64;

__device__ __forceinline__ u64 dup2(float x) {
    u64 r;
    asm("mov.b64 %0, {%1, %1};" : "=l"(r) : "f"(x));
    return r;
}

__device__ __forceinline__ u64 ffma2(u64 a, u64 b, u64 c) {
    u64 d;
    asm("fma.rn.f32x2 %0, %1, %2, %3;" : "=l"(d) : "l"(a), "l"(b), "l"(c));
    return d;
}

__device__ __forceinline__ float2 unpack2(u64 v) {
    float2 r;
    asm("mov.b64 {%0, %1}, %2;" : "=f"(r.x), "=f"(r.y) : "l"(v));
    return r;
}

__device__ __forceinline__ float silu_f(float x) {
    return x / (1.0f + __expf(-x));
}

__global__ void __launch_bounds__(256)
edge_mlp_kernel(const float* __restrict__ src,
                const float* __restrict__ dst,
                const float* __restrict__ edg,
                const float* __restrict__ W0, const float* __restrict__ b0,
                const float* __restrict__ W1, const float* __restrict__ b1,
                const float* __restrict__ W2, const float* __restrict__ b2,
                float* __restrict__ out, int E)
{
    // 32 KB: layer-0 x-chunk staging (64x33) UNION h activations (64x128).
    __shared__ __align__(16) float s_uni[TM * DH];
    // 16 KB: weight chunk (32 x 128)
    __shared__ __align__(16) float s_w[KC * DH];

    float (*xs)[KC + 1] = (float (*)[KC + 1])s_uni;  // 64 x 33 (padded)
    float (*hb)[DH]     = (float (*)[DH])s_uni;      // 64 x 128

    const int tid  = threadIdx.x;
    const int tx   = tid & 15;   // col-pair group: pairs {tx, tx+16, tx+32, tx+48}
    const int ty   = tid >> 4;   // row group: rows {ty, ty+16, ty+32, ty+48}
    const int row0 = blockIdx.x * TM;

    u64 acc[4][4];

    // ---------------- layer 0: cat[edge,src,dest] @ W0 ----------------
    #pragma unroll
    for (int i = 0; i < 4; i++)
        #pragma unroll
        for (int j = 0; j < 4; j++) acc[i][j] = 0ULL;

    for (int kc = 0; kc < 12; kc++) {
        const int ks = kc * KC;
        const float* xp;
        int koff;
        if (ks < DH)            { xp = edg; koff = ks; }
        else if (ks < 2 * DH)   { xp = src; koff = ks - DH; }
        else                    { xp = dst; koff = ks - 2 * DH; }

        // stage x chunk: 64 rows x 32 cols (512 float4, 2 per thread)
        #pragma unroll
        for (int t = 0; t < 2; t++) {
            int idx = tid + t * 256;
            int r = idx >> 3, c = (idx & 7) << 2;
            float4 v = make_float4(0.f, 0.f, 0.f, 0.f);
            int gr = row0 + r;
            if (gr < E) v = *(const float4*)(xp + gr * DH + koff + c);
            xs[r][c]     = v.x;
            xs[r][c + 1] = v.y;
            xs[r][c + 2] = v.z;
            xs[r][c + 3] = v.w;
        }
        // stage W0 chunk: 32 x 128 (1024 float4, 4 per thread)
        #pragma unroll
        for (int t = 0; t < 4; t++) {
            int idx = tid + t * 256;
            int r = idx >> 5, c = (idx & 31) << 2;
            *(float4*)&s_w[r * DH + c] = *(const float4*)(W0 + (ks + r) * DH + c);
        }
        __syncthreads();

        #pragma unroll 8
        for (int k = 0; k < KC; k++) {
            u64 a[4], b[4];
            #pragma unroll
            for (int i = 0; i < 4; i++) a[i] = dup2(xs[ty + 16 * i][k]);
            #pragma unroll
            for (int j = 0; j < 4; j++)
                b[j] = *(const u64*)&s_w[k * DH + 2 * (tx + 16 * j)];
            #pragma unroll
            for (int i = 0; i < 4; i++)
                #pragma unroll
                for (int j = 0; j < 4; j++)
                    acc[i][j] = ffma2(a[i], b[j], acc[i][j]);
        }
        __syncthreads();
    }

    // epilogue 0: +b0, SiLU -> hb (aliases xs; all xs reads are behind the sync)
    #pragma unroll
    for (int j = 0; j < 4; j++) {
        float2 bb = *(const float2*)(b0 + 2 * (tx + 16 * j));
        #pragma unroll
        for (int i = 0; i < 4; i++) {
            float2 v = unpack2(acc[i][j]);
            v.x = silu_f(v.x + bb.x);
            v.y = silu_f(v.y + bb.y);
            *(float2*)&hb[ty + 16 * i][2 * (tx + 16 * j)] = v;
        }
    }
    __syncthreads();

    // ---------------- layers 1 & 2: h @ W (K = 128) ----------------
    #pragma unroll 1
    for (int layer = 0; layer < 2; layer++) {
        const float* W = (layer == 0) ? W1 : W2;

        #pragma unroll
        for (int i = 0; i < 4; i++)
            #pragma unroll
            for (int j = 0; j < 4; j++) acc[i][j] = 0ULL;

        for (int kc = 0; kc < 4; kc++) {
            const int ks = kc * KC;
            #pragma unroll
            for (int t = 0; t < 4; t++) {
                int idx = tid + t * 256;
                int r = idx >> 5, c = (idx & 31) << 2;
                *(float4*)&s_w[r * DH + c] = *(const float4*)(W + (ks + r) * DH + c);
            }
            __syncthreads();

            #pragma unroll 8
            for (int k = 0; k < KC; k++) {
                u64 a[4], b[4];
                #pragma unroll
                for (int i = 0; i < 4; i++) a[i] = dup2(hb[ty + 16 * i][ks + k]);
                #pragma unroll
                for (int j = 0; j < 4; j++)
                    b[j] = *(const u64*)&s_w[k * DH + 2 * (tx + 16 * j)];
                #pragma unroll
                for (int i = 0; i < 4; i++)
                    #pragma unroll
                    for (int j = 0; j < 4; j++)
                        acc[i][j] = ffma2(a[i], b[j], acc[i][j]);
            }
            __syncthreads();
        }

        if (layer == 0) {
            // +b1, SiLU -> back into hb (all hb reads are behind the sync)
            #pragma unroll
            for (int j = 0; j < 4; j++) {
                float2 bb = *(const float2*)(b1 + 2 * (tx + 16 * j));
                #pragma unroll
                for (int i = 0; i < 4; i++) {
                    float2 v = unpack2(acc[i][j]);
                    v.x = silu_f(v.x + bb.x);
                    v.y = silu_f(v.y + bb.y);
                    *(float2*)&hb[ty + 16 * i][2 * (tx + 16 * j)] = v;
                }
            }
            __syncthreads();
        } else {
            // final: +b2, store to GMEM (guard partial last tile)
            #pragma unroll
            for (int j = 0; j < 4; j++) {
                float2 bb = *(const float2*)(b2 + 2 * (tx + 16 * j));
                #pragma unroll
                for (int i = 0; i < 4; i++) {
                    int gr = row0 + ty + 16 * i;
                    if (gr < E) {
                        float2 v = unpack2(acc[i][j]);
                        v.x += bb.x;
                        v.y += bb.y;
                        *(float2*)(out + gr * DH + 2 * (tx + 16 * j)) = v;
                    }
                }
            }
        }
    }
}

extern "C" void kernel_launch(void* const* d_in, const int* in_sizes, int n_in,
                              void* d_out, int out_size) {
    const float* src = (const float*)d_in[0];
    const float* dst = (const float*)d_in[1];
    const float* edg = (const float*)d_in[2];
    const float* W0  = (const float*)d_in[3];
    const float* b0  = (const float*)d_in[4];
    const float* W1  = (const float*)d_in[5];
    const float* b1  = (const float*)d_in[6];
    const float* W2  = (const float*)d_in[7];
    const float* b2  = (const float*)d_in[8];

    int E = in_sizes[0] / DH;               // src is [E, 128]
    int blocks = (E + TM - 1) / TM;

    edge_mlp_kernel<<<blocks, 256>>>(src, dst, edg, W0, b0, W1, b1, W2, b2,
                                     (float*)d_out, E);
}

// round 8
// speedup vs baseline: 1.2740x; 1.2740x over previous
#include <cuda_runtime.h>
#include <cuda_bf16.h>
#include <cstdint>

// EdgeModel fused 3-layer MLP on tensor cores via arch-agnostic mma.sync
// (tcgen05 is NOT available: harness compiles at compute_103, no 'a' suffix).
//
// Math: fp32 -> bf16 hi/lo split; D = Ah*Bh + Al*Bh + Ah*Bl (drop Al*Bl).
// Tiles: CTA = 128 rows x 128 cols, 8 warps (4M x 2N), warp tile 32x64.
// A and B both stored k-pair-packed u32 [rows][kp] with row pad 68 so that
// ldmatrix.x4 fragment loads are bank-conflict-free.

#define DH 128
#define APAD 68
#define CHUNK_U32 (128 * APAD)       // one 128x(64kp) buffer
#define CHUNK_BYTES (CHUNK_U32 * 4)  // 34816

// weight images: 5 regions (W0 k-chunks 0..2, W1, W2) x {hi,lo} x [n][kp]
__device__ __align__(16) uint32_t g_wp[5][2][128][APAD];

// ---------------- helpers ----------------
__device__ __forceinline__ uint32_t smem_u32(const void* p) {
    uint32_t a;
    asm("{ .reg .u64 t; cvta.to.shared.u64 t, %1; cvt.u32.u64 %0, t; }"
        : "=r"(a) : "l"(p));
    return a;
}

__device__ __forceinline__ uint32_t pack_bf2(float a0, float a1, uint32_t* lo_out) {
    __nv_bfloat16 h0 = __float2bfloat16(a0);
    __nv_bfloat16 h1 = __float2bfloat16(a1);
    __nv_bfloat16 l0 = __float2bfloat16(a0 - __bfloat162float(h0));
    __nv_bfloat16 l1 = __float2bfloat16(a1 - __bfloat162float(h1));
    *lo_out = (uint32_t)__bfloat16_as_ushort(l0) |
              ((uint32_t)__bfloat16_as_ushort(l1) << 16);
    return (uint32_t)__bfloat16_as_ushort(h0) |
           ((uint32_t)__bfloat16_as_ushort(h1) << 16);
}

__device__ __forceinline__ float silu_f(float x) {
    return x / (1.0f + __expf(-x));
}

#define LDSM4(r, addr)                                                         \
    asm volatile("ldmatrix.sync.aligned.m8n8.x4.shared.b16 {%0,%1,%2,%3}, [%4];" \
        : "=r"((r)[0]), "=r"((r)[1]), "=r"((r)[2]), "=r"((r)[3]) : "r"(addr))

#define MMA16816(c, a, b)                                                      \
    asm volatile("mma.sync.aligned.m16n8k16.row.col.f32.bf16.bf16.f32 "        \
        "{%0,%1,%2,%3}, {%4,%5,%6,%7}, {%8,%9}, {%0,%1,%2,%3};"                \
        : "+f"((c)[0]), "+f"((c)[1]), "+f"((c)[2]), "+f"((c)[3])               \
        : "r"((a)[0]), "r"((a)[1]), "r"((a)[2]), "r"((a)[3]),                  \
          "r"((b)[0]), "r"((b)[1]))

// ---------------- prep: pack weights into hi/lo ldmatrix-ready images -------
__global__ void prep_weights(const float* __restrict__ W0,
                             const float* __restrict__ W1,
                             const float* __restrict__ W2) {
    int i = blockIdx.x * blockDim.x + threadIdx.x;
    if (i >= 5 * 128 * 64) return;
    int r   = i >> 13;          // / (128*64)
    int rem = i & 8191;
    int n   = rem >> 6;
    int kp  = rem & 63;
    const float* W = (r < 3) ? W0 : (r == 3) ? W1 : W2;
    int k0 = ((r < 3) ? r * 128 : 0) + 2 * kp;
    float v0 = W[(size_t)k0 * DH + n];
    float v1 = W[(size_t)(k0 + 1) * DH + n];
    uint32_t lo;
    uint32_t hi = pack_bf2(v0, v1, &lo);
    g_wp[r][0][n][kp] = hi;
    g_wp[r][1][n][kp] = lo;
}

// ---------------- fused MLP kernel ----------------
struct LaneCtx {
    uint32_t aHi, aLo, bHi, bLo;   // per-lane base byte addresses in SMEM
};

__device__ __forceinline__ void mma_chunk(float acc[2][8][4], const LaneCtx& cx) {
    #pragma unroll 2
    for (int ks = 0; ks < 8; ks++) {
        uint32_t ah[2][4], al[2][4], bh[4][4], bl[4][4];
        #pragma unroll
        for (int mt = 0; mt < 2; mt++) {
            uint32_t off = mt * (16 * APAD * 4) + ks * 32;
            LDSM4(ah[mt], cx.aHi + off);
            LDSM4(al[mt], cx.aLo + off);
        }
        #pragma unroll
        for (int jj = 0; jj < 4; jj++) {
            uint32_t off = jj * (16 * APAD * 4) + ks * 32;
            LDSM4(bh[jj], cx.bHi + off);
            LDSM4(bl[jj], cx.bLo + off);
        }
        #pragma unroll
        for (int mt = 0; mt < 2; mt++)
            #pragma unroll
            for (int nt = 0; nt < 8; nt++) {
                const uint32_t* pbh = &bh[nt >> 1][(nt & 1) * 2];
                const uint32_t* pbl = &bl[nt >> 1][(nt & 1) * 2];
                MMA16816(acc[mt][nt], ah[mt], pbh);   // Ah*Bh
                MMA16816(acc[mt][nt], al[mt], pbh);   // Al*Bh
                MMA16816(acc[mt][nt], ah[mt], pbl);   // Ah*Bl
            }
    }
}

__global__ void __launch_bounds__(256)
mlp_kernel(const float* __restrict__ src, const float* __restrict__ dst,
           const float* __restrict__ edg,
           const float* __restrict__ b0, const float* __restrict__ b1,
           const float* __restrict__ b2,
           float* __restrict__ out, int E)
{
    extern __shared__ uint32_t sm[];
    uint32_t* Ahi = sm;
    uint32_t* Alo = sm + CHUNK_U32;
    uint32_t* Bbuf = sm + 2 * CHUNK_U32;     // Bhi then Blo, contiguous

    const int tid = threadIdx.x;
    const int l = tid & 31, w = tid >> 5;
    const int warp_m = (w & 3) * 32;
    const int warp_n = (w >> 2) * 64;
    const int tile = blockIdx.x;

    const uint32_t smb  = smem_u32(sm);
    const uint32_t aHiB = smb;
    const uint32_t aLoB = smb + CHUNK_BYTES;
    const uint32_t bHiB = smb + 2 * CHUNK_BYTES;
    const uint32_t bLoB = smb + 3 * CHUNK_BYTES;

    // ldmatrix per-lane offsets (A row-major frags; B from transposed image)
    const int laneA_r = (l & 7) + ((l >> 3) & 1) * 8;
    const int laneA_k = ((l >> 4) & 1) * 4;
    const int laneB_r = (l & 7) + ((l >> 4) & 1) * 8;
    const int laneB_k = ((l >> 3) & 1) * 4;
    const uint32_t aoff = ((warp_m + laneA_r) * APAD + laneA_k) * 4;
    const uint32_t boff = ((warp_n + laneB_r) * APAD + laneB_k) * 4;
    LaneCtx cx = { aHiB + aoff, aLoB + aoff, bHiB + boff, bLoB + boff };

    float acc[2][8][4];
    #pragma unroll
    for (int mt = 0; mt < 2; mt++)
        #pragma unroll
        for (int nt = 0; nt < 8; nt++)
            #pragma unroll
            for (int q = 0; q < 4; q++) acc[mt][nt][q] = 0.f;

    // A staging map: thread -> (row, half of 64 kp)
    const int srow = tid >> 1, shalf = tid & 1;
    const int grow_s = tile * 128 + srow;
    const bool svalid = grow_s < E;

    // epilogue lane constants
    const int er0 = (l >> 2);          // +warp_m +16*mt; second row +8
    const int ec  = (l & 3) * 2;       // +warp_n +8*nt
    const int ecp = (warp_n >> 1) + (l & 3);

    // ================= layer 0: 3 k-chunks (edge, src, dest) ================
    #pragma unroll 1
    for (int c = 0; c < 3; c++) {
        const float* xp = (c == 0) ? edg : (c == 1) ? src : dst;
        // stage A chunk (fp32 -> bf16 hi/lo packed)
        {
            const float4* p = (const float4*)(xp + (size_t)grow_s * DH + shalf * 64);
            #pragma unroll
            for (int q = 0; q < 16; q++) {
                float4 v = svalid ? p[q] : make_float4(0.f, 0.f, 0.f, 0.f);
                uint32_t lo0, lo1;
                uint32_t h0 = pack_bf2(v.x, v.y, &lo0);
                uint32_t h1 = pack_bf2(v.z, v.w, &lo1);
                int kp = shalf * 32 + 2 * q;
                Ahi[srow * APAD + kp]     = h0;
                Ahi[srow * APAD + kp + 1] = h1;
                Alo[srow * APAD + kp]     = lo0;
                Alo[srow * APAD + kp + 1] = lo1;
            }
        }
        // copy B chunk (hi+lo contiguous)
        {
            const uint4* s = (const uint4*)&g_wp[c][0][0][0];
            uint4* d = (uint4*)Bbuf;
            #pragma unroll 1
            for (int i = tid; i < 2 * CHUNK_U32 / 4; i += 256) d[i] = s[i];
        }
        __syncthreads();
        mma_chunk(acc, cx);
        __syncthreads();
    }

    // =============== layers 1 & 2 ===============
    #pragma unroll 1
    for (int layer = 1; layer <= 2; layer++) {
        const float* bias = (layer == 1) ? b0 : b1;   // bias of the PREVIOUS gemm
        // epilogue: silu(acc + bias) -> A hi/lo ; reset acc
        #pragma unroll
        for (int mt = 0; mt < 2; mt++)
            #pragma unroll
            for (int nt = 0; nt < 8; nt++) {
                int col = warp_n + 8 * nt + ec;
                float bb0 = __ldg(bias + col), bb1 = __ldg(bias + col + 1);
                int r0 = warp_m + 16 * mt + er0;
                int cp = ecp + 4 * nt;
                float h00 = silu_f(acc[mt][nt][0] + bb0);
                float h01 = silu_f(acc[mt][nt][1] + bb1);
                float h10 = silu_f(acc[mt][nt][2] + bb0);
                float h11 = silu_f(acc[mt][nt][3] + bb1);
                uint32_t lo0, lo1;
                uint32_t hi0 = pack_bf2(h00, h01, &lo0);
                uint32_t hi1 = pack_bf2(h10, h11, &lo1);
                Ahi[r0 * APAD + cp]       = hi0;
                Alo[r0 * APAD + cp]       = lo0;
                Ahi[(r0 + 8) * APAD + cp] = hi1;
                Alo[(r0 + 8) * APAD + cp] = lo1;
                acc[mt][nt][0] = 0.f; acc[mt][nt][1] = 0.f;
                acc[mt][nt][2] = 0.f; acc[mt][nt][3] = 0.f;
            }
        // copy W1 / W2 image
        {
            int region = (layer == 1) ? 3 : 4;
            const uint4* s = (const uint4*)&g_wp[region][0][0][0];
            uint4* d = (uint4*)Bbuf;
            #pragma unroll 1
            for (int i = tid; i < 2 * CHUNK_U32 / 4; i += 256) d[i] = s[i];
        }
        __syncthreads();
        mma_chunk(acc, cx);
        __syncthreads();
    }

    // =============== final epilogue: acc + b2 -> out ===============
    #pragma unroll
    for (int mt = 0; mt < 2; mt++)
        #pragma unroll
        for (int nt = 0; nt < 8; nt++) {
            int col = warp_n + 8 * nt + ec;
            float bb0 = __ldg(b2 + col), bb1 = __ldg(b2 + col + 1);
            int r0g = tile * 128 + warp_m + 16 * mt + er0;
            if (r0g < E) {
                float2 v = { acc[mt][nt][0] + bb0, acc[mt][nt][1] + bb1 };
                *(float2*)(out + (size_t)r0g * DH + col) = v;
            }
            if (r0g + 8 < E) {
                float2 v = { acc[mt][nt][2] + bb0, acc[mt][nt][3] + bb1 };
                *(float2*)(out + (size_t)(r0g + 8) * DH + col) = v;
            }
        }
}

// ---------------- host ----------------
#define SMEM_TOTAL (4 * CHUNK_BYTES)   // 139264

extern "C" void kernel_launch(void* const* d_in, const int* in_sizes, int n_in,
                              void* d_out, int out_size) {
    const float* src = (const float*)d_in[0];
    const float* dst = (const float*)d_in[1];
    const float* edg = (const float*)d_in[2];
    const float* W0  = (const float*)d_in[3];
    const float* b0  = (const float*)d_in[4];
    const float* W1  = (const float*)d_in[5];
    const float* b1  = (const float*)d_in[6];
    const float* W2  = (const float*)d_in[7];
    const float* b2  = (const float*)d_in[8];

    int E = in_sizes[0] / DH;
    int ntiles = (E + 127) / 128;

    cudaFuncSetAttribute(mlp_kernel, cudaFuncAttributeMaxDynamicSharedMemorySize,
                         SMEM_TOTAL);

    prep_weights<<<(5 * 128 * 64 + 255) / 256, 256>>>(W0, W1, W2);
    mlp_kernel<<<ntiles, 256, SMEM_TOTAL>>>(src, dst, edg, b0, b1, b2,
                                            (float*)d_out, E);
}

// round 10
// speedup vs baseline: 2.0435x; 1.6040x over previous
#include <cuda_runtime.h>
#include <cuda_bf16.h>
#include <cstdint>

// EdgeModel fused 3-layer MLP via arch-agnostic mma.sync (bf16 3-term split).
// R9: M-tile 128->64 so SMEM 136KB->102KB -> 2 CTAs/SM (occupancy was the
// R8 bottleneck: tensor=28%, occ=12.5%, 1 CTA/SM phase-serialized).
// B staged with cp.async.cg. Warp tile 32x32 (8 warps = 2M x 4N).

#define DH 128
#define TM 64
#define APAD 68
#define A_U32 (TM * APAD)            // 4352
#define B_U32 (128 * APAD)           // 8704
#define SMEM_TOTAL ((2 * A_U32 + 2 * B_U32) * 4)   // 104448 B

// weight images: 5 regions (W0 k-chunks 0..2, W1, W2) x {hi,lo} x [n][kp]
__device__ __align__(16) uint32_t g_wp[5][2][128][APAD];

// ---------------- helpers ----------------
__device__ __forceinline__ uint32_t smem_u32(const void* p) {
    uint32_t a;
    asm("{ .reg .u64 t; cvta.to.shared.u64 t, %1; cvt.u32.u64 %0, t; }"
        : "=r"(a) : "l"(p));
    return a;
}

__device__ __forceinline__ uint32_t pack_bf2(float a0, float a1, uint32_t* lo_out) {
    __nv_bfloat16 h0 = __float2bfloat16(a0);
    __nv_bfloat16 h1 = __float2bfloat16(a1);
    __nv_bfloat16 l0 = __float2bfloat16(a0 - __bfloat162float(h0));
    __nv_bfloat16 l1 = __float2bfloat16(a1 - __bfloat162float(h1));
    *lo_out = (uint32_t)__bfloat16_as_ushort(l0) |
              ((uint32_t)__bfloat16_as_ushort(l1) << 16);
    return (uint32_t)__bfloat16_as_ushort(h0) |
           ((uint32_t)__bfloat16_as_ushort(h1) << 16);
}

__device__ __forceinline__ float silu_f(float x) {
    return x / (1.0f + __expf(-x));
}

#define LDSM4(r, addr)                                                         \
    asm volatile("ldmatrix.sync.aligned.m8n8.x4.shared.b16 {%0,%1,%2,%3}, [%4];" \
        : "=r"((r)[0]), "=r"((r)[1]), "=r"((r)[2]), "=r"((r)[3]) : "r"(addr))

#define MMA16816(c, a, b)                                                      \
    asm volatile("mma.sync.aligned.m16n8k16.row.col.f32.bf16.bf16.f32 "        \
        "{%0,%1,%2,%3}, {%4,%5,%6,%7}, {%8,%9}, {%0,%1,%2,%3};"                \
        : "+f"((c)[0]), "+f"((c)[1]), "+f"((c)[2]), "+f"((c)[3])               \
        : "r"((a)[0]), "r"((a)[1]), "r"((a)[2]), "r"((a)[3]),                  \
          "r"((b)[0]), "r"((b)[1]))

#define CP_ASYNC16(sm_addr, gptr)                                              \
    asm volatile("cp.async.cg.shared.global [%0], [%1], 16;"                   \
        :: "r"(sm_addr), "l"(gptr) : "memory")
#define CP_COMMIT()  asm volatile("cp.async.commit_group;" ::: "memory")
#define CP_WAIT0()   asm volatile("cp.async.wait_group 0;" ::: "memory")

// ---------------- prep: pack weights into hi/lo ldmatrix-ready images -------
__global__ void prep_weights(const float* __restrict__ W0,
                             const float* __restrict__ W1,
                             const float* __restrict__ W2) {
    int i = blockIdx.x * blockDim.x + threadIdx.x;
    if (i >= 5 * 128 * 64) return;
    int r   = i >> 13;
    int rem = i & 8191;
    int n   = rem >> 6;
    int kp  = rem & 63;
    const float* W = (r < 3) ? W0 : (r == 3) ? W1 : W2;
    int k0 = ((r < 3) ? r * 128 : 0) + 2 * kp;
    float v0 = W[(size_t)k0 * DH + n];
    float v1 = W[(size_t)(k0 + 1) * DH + n];
    uint32_t lo;
    uint32_t hi = pack_bf2(v0, v1, &lo);
    g_wp[r][0][n][kp] = hi;
    g_wp[r][1][n][kp] = lo;
}

// ---------------- fused MLP kernel ----------------
struct LaneCtx {
    uint32_t aHi, aLo, bHi, bLo;
};

__device__ __forceinline__ void mma_chunk(float acc[2][4][4], const LaneCtx& cx) {
    #pragma unroll 2
    for (int ks = 0; ks < 8; ks++) {
        uint32_t ah[2][4], al[2][4], bh[2][4], bl[2][4];
        #pragma unroll
        for (int mt = 0; mt < 2; mt++) {
            uint32_t off = mt * (16 * APAD * 4) + ks * 32;
            LDSM4(ah[mt], cx.aHi + off);
            LDSM4(al[mt], cx.aLo + off);
        }
        #pragma unroll
        for (int jj = 0; jj < 2; jj++) {
            uint32_t off = jj * (16 * APAD * 4) + ks * 32;
            LDSM4(bh[jj], cx.bHi + off);
            LDSM4(bl[jj], cx.bLo + off);
        }
        #pragma unroll
        for (int mt = 0; mt < 2; mt++)
            #pragma unroll
            for (int nt = 0; nt < 4; nt++) {
                const uint32_t* pbh = &bh[nt >> 1][(nt & 1) * 2];
                const uint32_t* pbl = &bl[nt >> 1][(nt & 1) * 2];
                MMA16816(acc[mt][nt], ah[mt], pbh);   // Ah*Bh
                MMA16816(acc[mt][nt], al[mt], pbh);   // Al*Bh
                MMA16816(acc[mt][nt], ah[mt], pbl);   // Ah*Bl
            }
    }
}

__global__ void __launch_bounds__(256)
mlp_kernel(const float* __restrict__ src, const float* __restrict__ dst,
           const float* __restrict__ edg,
           const float* __restrict__ b0, const float* __restrict__ b1,
           const float* __restrict__ b2,
           float* __restrict__ out, int E)
{
    extern __shared__ uint32_t sm[];
    uint32_t* Ahi = sm;
    uint32_t* Alo = sm + A_U32;
    // Bhi then Blo, contiguous (matches g_wp region layout)
    const uint32_t smb  = smem_u32(sm);
    const uint32_t aHiB = smb;
    const uint32_t aLoB = smb + A_U32 * 4;
    const uint32_t bHiB = smb + 2 * A_U32 * 4;
    const uint32_t bLoB = bHiB + B_U32 * 4;

    const int tid = threadIdx.x;
    const int l = tid & 31, w = tid >> 5;
    const int warp_m = (w & 1) * 32;
    const int warp_n = (w >> 1) * 32;
    const int tile = blockIdx.x;

    // ldmatrix per-lane offsets (verified mapping from R8)
    const int laneA_r = (l & 7) + ((l >> 3) & 1) * 8;
    const int laneA_k = ((l >> 4) & 1) * 4;
    const int laneB_r = (l & 7) + ((l >> 4) & 1) * 8;
    const int laneB_k = ((l >> 3) & 1) * 4;
    const uint32_t aoff = ((warp_m + laneA_r) * APAD + laneA_k) * 4;
    const uint32_t boff = ((warp_n + laneB_r) * APAD + laneB_k) * 4;
    LaneCtx cx = { aHiB + aoff, aLoB + aoff, bHiB + boff, bLoB + boff };

    float acc[2][4][4];
    #pragma unroll
    for (int mt = 0; mt < 2; mt++)
        #pragma unroll
        for (int nt = 0; nt < 4; nt++)
            #pragma unroll
            for (int q = 0; q < 4; q++) acc[mt][nt][q] = 0.f;

    // A staging map: thread -> (row, quarter of 64 kp)
    const int srow = tid >> 2, sq = tid & 3;
    const int grow_s = tile * TM + srow;
    const bool svalid = grow_s < E;

    // epilogue lane constants
    const int er0 = (l >> 2);
    const int ec  = (l & 3) * 2;
    const int ecp = (warp_n >> 1) + (l & 3);

    // ================= layer 0: 3 k-chunks (edge, src, dest) ================
    #pragma unroll 1
    for (int c = 0; c < 3; c++) {
        const float* xp = (c == 0) ? edg : (c == 1) ? src : dst;
        // issue async B copy first so it overlaps the A convert
        {
            const uint4* s = (const uint4*)&g_wp[c][0][0][0];
            #pragma unroll 1
            for (int i = tid; i < 2 * B_U32 / 4; i += 256)
                CP_ASYNC16(bHiB + i * 16, s + i);
            CP_COMMIT();
        }
        // stage A chunk (fp32 -> bf16 hi/lo packed)
        {
            const float4* p = (const float4*)(xp + (size_t)grow_s * DH + sq * 32);
            #pragma unroll
            for (int q = 0; q < 8; q++) {
                float4 v = svalid ? p[q] : make_float4(0.f, 0.f, 0.f, 0.f);
                uint32_t lo0, lo1;
                uint32_t h0 = pack_bf2(v.x, v.y, &lo0);
                uint32_t h1 = pack_bf2(v.z, v.w, &lo1);
                int kp = sq * 16 + 2 * q;
                Ahi[srow * APAD + kp]     = h0;
                Ahi[srow * APAD + kp + 1] = h1;
                Alo[srow * APAD + kp]     = lo0;
                Alo[srow * APAD + kp + 1] = lo1;
            }
        }
        CP_WAIT0();
        __syncthreads();
        mma_chunk(acc, cx);
        __syncthreads();
    }

    // =============== layers 1 & 2 ===============
    #pragma unroll 1
    for (int layer = 1; layer <= 2; layer++) {
        const float* bias = (layer == 1) ? b0 : b1;   // bias of the PREVIOUS gemm
        // issue async W copy first
        {
            int region = (layer == 1) ? 3 : 4;
            const uint4* s = (const uint4*)&g_wp[region][0][0][0];
            #pragma unroll 1
            for (int i = tid; i < 2 * B_U32 / 4; i += 256)
                CP_ASYNC16(bHiB + i * 16, s + i);
            CP_COMMIT();
        }
        // epilogue: silu(acc + bias) -> A hi/lo ; reset acc
        #pragma unroll
        for (int mt = 0; mt < 2; mt++)
            #pragma unroll
            for (int nt = 0; nt < 4; nt++) {
                int col = warp_n + 8 * nt + ec;
                float bb0 = __ldg(bias + col), bb1 = __ldg(bias + col + 1);
                int r0 = warp_m + 16 * mt + er0;
                int cp = ecp + 4 * nt;
                float h00 = silu_f(acc[mt][nt][0] + bb0);
                float h01 = silu_f(acc[mt][nt][1] + bb1);
                float h10 = silu_f(acc[mt][nt][2] + bb0);
                float h11 = silu_f(acc[mt][nt][3] + bb1);
                uint32_t lo0, lo1;
                uint32_t hi0 = pack_bf2(h00, h01, &lo0);
                uint32_t hi1 = pack_bf2(h10, h11, &lo1);
                Ahi[r0 * APAD + cp]       = hi0;
                Alo[r0 * APAD + cp]       = lo0;
                Ahi[(r0 + 8) * APAD + cp] = hi1;
                Alo[(r0 + 8) * APAD + cp] = lo1;
                acc[mt][nt][0] = 0.f; acc[mt][nt][1] = 0.f;
                acc[mt][nt][2] = 0.f; acc[mt][nt][3] = 0.f;
            }
        CP_WAIT0();
        __syncthreads();
        mma_chunk(acc, cx);
        __syncthreads();
    }

    // =============== final epilogue: acc + b2 -> out ===============
    #pragma unroll
    for (int mt = 0; mt < 2; mt++)
        #pragma unroll
        for (int nt = 0; nt < 4; nt++) {
            int col = warp_n + 8 * nt + ec;
            float bb0 = __ldg(b2 + col), bb1 = __ldg(b2 + col + 1);
            int r0g = tile * TM + warp_m + 16 * mt + er0;
            if (r0g < E) {
                float2 v = { acc[mt][nt][0] + bb0, acc[mt][nt][1] + bb1 };
                *(float2*)(out + (size_t)r0g * DH + col) = v;
            }
            if (r0g + 8 < E) {
                float2 v = { acc[mt][nt][2] + bb0, acc[mt][nt][3] + bb1 };
                *(float2*)(out + (size_t)(r0g + 8) * DH + col) = v;
            }
        }
}

// ---------------- host ----------------
extern "C" void kernel_launch(void* const* d_in, const int* in_sizes, int n_in,
                              void* d_out, int out_size) {
    const float* src = (const float*)d_in[0];
    const float* dst = (const float*)d_in[1];
    const float* edg = (const float*)d_in[2];
    const float* W0  = (const float*)d_in[3];
    const float* b0  = (const float*)d_in[4];
    const float* W1  = (const float*)d_in[5];
    const float* b1  = (const float*)d_in[6];
    const float* W2  = (const float*)d_in[7];
    const float* b2  = (const float*)d_in[8];

    int E = in_sizes[0] / DH;
    int ntiles = (E + TM - 1) / TM;

    cudaFuncSetAttribute(mlp_kernel, cudaFuncAttributeMaxDynamicSharedMemorySize,
                         SMEM_TOTAL);

    prep_weights<<<(5 * 128 * 64 + 255) / 256, 256>>>(W0, W1, W2);
    mlp_kernel<<<ntiles, 256, SMEM_TOTAL>>>(src, dst, edg, b0, b1, b2,
                                            (float*)d_out, E);
}